// round 6
// baseline (speedup 1.0000x reference)
#include <cuda_runtime.h>

#define DIM   100
#define KBS   4950
#define NN    (DIM * DIM)          // 10000
#define MAXB  2048                 // max supported batch
#define KC    25                   // K-chunk
#define ASTR  (KC + 1)             // 26, padded
#define BSTR  (DIM + 1)            // 101, padded

// Clamp for loads: always lands in-bounds.
#define CLAMP(i, n) ((i) < (n) ? (i) : ((n) - 1))

// Sanctioned scratch (__device__ globals; no runtime allocation).
__device__ float2 g_U[NN];
__device__ float2 g_L[MAXB * NN];

// ---------------------------------------------------------------------------
// Kernel 1: build U = D * T_K ... T_1.  One CTA per column.
// ---------------------------------------------------------------------------
__global__ void build_U(const float* __restrict__ theta,
                        const float* __restrict__ phi,
                        const float* __restrict__ diag,
                        int n_th, int n_ph, int n_dg) {
    __shared__ float2 col[DIM];
    const int c   = CLAMP(blockIdx.x, DIM);
    const int tid = threadIdx.x;

    for (int r = tid; r < DIM; r += blockDim.x)
        col[CLAMP(r, DIM)] = make_float2(r == c ? 1.0f : 0.0f, 0.0f);
    __syncthreads();

    int off = 0;
    for (int layer = 0; layer < DIM; ++layer) {
        const int start = layer & 1;
        const int np    = (DIM - start) >> 1;
        if (tid < np) {
            const int m  = CLAMP(start + 2 * tid, DIM - 1);
            const int gi = off + tid;
            const float th = theta[CLAMP(gi, n_th)];
            const float ph = phi[CLAMP(gi, n_ph)];
            const float cc = cosf(th);
            const float ss = sinf(th);
            float sp, cp;
            sincosf(ph, &sp, &cp);
            const float2 rm = col[m];
            const float2 rn = col[m + 1];
            const float er = cp * rm.x - sp * rm.y;   // e^{i ph} * rm
            const float ei = cp * rm.y + sp * rm.x;
            col[m]     = make_float2(cc * er - ss * rn.x, cc * ei - ss * rn.y);
            col[m + 1] = make_float2(ss * er + cc * rn.x, ss * ei + cc * rn.y);
        }
        off += np;
        __syncthreads();
    }

    for (int r = tid; r < DIM; r += blockDim.x) {
        float sp, cp;
        sincosf(diag[CLAMP(r, n_dg)], &sp, &cp);
        const float2 v = col[CLAMP(r, DIM)];
        const int gi = r * DIM + c;
        if (gi < NN)
            g_U[gi] = make_float2(cp * v.x - sp * v.y,
                                  cp * v.y + sp * v.x);
    }
}

// ---------------------------------------------------------------------------
// Kernel 2: GEMM1  L_b = U @ X_b.  One CTA per batch, 500 active threads,
// 5x4 complex microtiles, K-chunked, static smem 41.0 KB.
// ---------------------------------------------------------------------------
__global__ void __launch_bounds__(512, 1)
gemm1_UX(const float* __restrict__ xre,
         const float* __restrict__ xim,
         int x_elems, int l_elems) {
    __shared__ float2 As[DIM * ASTR];   // U rows   [row][kk]
    __shared__ float2 Bs[KC * BSTR];    // X chunk  [kk][col]

    const int b    = blockIdx.x;
    const int tid  = threadIdx.x;
    const int base = b * NN;

    const bool active = tid < 500;
    const int ti = tid / 25;
    const int tj = tid - ti * 25;
    const int i0 = ti * 5;
    const int j0 = tj * 4;

    float accx[5][4], accy[5][4];
    #pragma unroll
    for (int r = 0; r < 5; ++r)
        #pragma unroll
        for (int c = 0; c < 4; ++c) { accx[r][c] = 0.0f; accy[r][c] = 0.0f; }

    for (int kc = 0; kc < DIM; kc += KC) {
        for (int e = tid; e < DIM * KC; e += blockDim.x) {
            const int row = e / KC;
            const int kk  = e - row * KC;
            As[CLAMP(row * ASTR + kk, DIM * ASTR)] =
                g_U[CLAMP(row * DIM + kc + kk, NN)];
        }
        for (int e = tid; e < KC * DIM; e += blockDim.x) {
            const int kk  = e / DIM;
            const int col = e - kk * DIM;
            const int gidx = CLAMP(base + (kc + kk) * DIM + col, x_elems);
            Bs[CLAMP(kk * BSTR + col, KC * BSTR)] =
                make_float2(xre[gidx], xim[gidx]);
        }
        __syncthreads();

        if (active) {
            #pragma unroll
            for (int kk = 0; kk < KC; ++kk) {
                float2 a[5], bb[4];
                #pragma unroll
                for (int r = 0; r < 5; ++r)
                    a[r] = As[CLAMP((i0 + r) * ASTR + kk, DIM * ASTR)];
                #pragma unroll
                for (int c = 0; c < 4; ++c)
                    bb[c] = Bs[CLAMP(kk * BSTR + j0 + c, KC * BSTR)];
                #pragma unroll
                for (int r = 0; r < 5; ++r)
                    #pragma unroll
                    for (int c = 0; c < 4; ++c) {
                        accx[r][c] = fmaf(a[r].x, bb[c].x,
                                     fmaf(-a[r].y, bb[c].y, accx[r][c]));
                        accy[r][c] = fmaf(a[r].x, bb[c].y,
                                     fmaf( a[r].y, bb[c].x, accy[r][c]));
                    }
            }
        }
        __syncthreads();
    }

    if (active) {
        #pragma unroll
        for (int r = 0; r < 5; ++r)
            #pragma unroll
            for (int c = 0; c < 4; ++c) {
                const int idx = base + (i0 + r) * DIM + (j0 + c);
                if (idx < l_elems)
                    g_L[idx] = make_float2(accx[r][c], accy[r][c]);
            }
    }
}

// ---------------------------------------------------------------------------
// Kernel 3: GEMM2  O_b = L_b @ U^H.  Static smem 41.6 KB.
// Output stage is mode-driven:
//   mode 0: store Re(O) only as float  (output dtype float32, out_size=B*N*N)
//   mode 1: store interleaved complex as float2 (buffer holds 2*B*N*N floats)
// All stores bounded by out_floats (capacity in FLOAT units).
// ---------------------------------------------------------------------------
__global__ void __launch_bounds__(512, 1)
gemm2_LUh(float* __restrict__ outf, int out_floats, int mode, int l_elems) {
    __shared__ float2 As[DIM * ASTR];   // L rows  [i][kk]
    __shared__ float2 Us[DIM * ASTR];   // U rows  [j][kk]

    const int b    = blockIdx.x;
    const int tid  = threadIdx.x;
    const int base = b * NN;

    const bool active = tid < 500;
    const int ti = tid / 25;
    const int tj = tid - ti * 25;
    const int i0 = ti * 5;
    const int j0 = tj * 4;

    float ox[5][4], oy[5][4];
    #pragma unroll
    for (int r = 0; r < 5; ++r)
        #pragma unroll
        for (int c = 0; c < 4; ++c) { ox[r][c] = 0.0f; oy[r][c] = 0.0f; }

    for (int kc = 0; kc < DIM; kc += KC) {
        for (int e = tid; e < DIM * KC; e += blockDim.x) {
            const int row = e / KC;
            const int kk  = e - row * KC;
            As[CLAMP(row * ASTR + kk, DIM * ASTR)] =
                g_L[CLAMP(base + row * DIM + kc + kk, l_elems)];
            Us[CLAMP(row * ASTR + kk, DIM * ASTR)] =
                g_U[CLAMP(row * DIM + kc + kk, NN)];
        }
        __syncthreads();

        if (active) {
            #pragma unroll
            for (int kk = 0; kk < KC; ++kk) {
                float2 a[5], u[4];
                #pragma unroll
                for (int r = 0; r < 5; ++r)
                    a[r] = As[CLAMP((i0 + r) * ASTR + kk, DIM * ASTR)];
                #pragma unroll
                for (int c = 0; c < 4; ++c)
                    u[c] = Us[CLAMP((j0 + c) * ASTR + kk, DIM * ASTR)];
                #pragma unroll
                for (int r = 0; r < 5; ++r)
                    #pragma unroll
                    for (int c = 0; c < 4; ++c) {
                        // a * conj(u)
                        ox[r][c] = fmaf(a[r].x, u[c].x,
                                   fmaf( a[r].y, u[c].y, ox[r][c]));
                        oy[r][c] = fmaf(a[r].y, u[c].x,
                                   fmaf(-a[r].x, u[c].y, oy[r][c]));
                    }
            }
        }
        __syncthreads();
    }

    if (active) {
        #pragma unroll
        for (int r = 0; r < 5; ++r)
            #pragma unroll
            for (int c = 0; c < 4; ++c) {
                const int idx = base + (i0 + r) * DIM + (j0 + c);
                if (mode == 0) {
                    if (idx < out_floats)
                        outf[idx] = ox[r][c];                 // real part only
                } else {
                    if (2 * idx + 1 < out_floats)
                        reinterpret_cast<float2*>(outf)[idx] =
                            make_float2(ox[r][c], oy[r][c]);  // interleaved
                }
            }
    }
}

// Diagnostic fallback: binding anomaly -> numeric mismatch, never a crash.
__global__ void diag_mark_kernel(float* out) { out[0] = 0.0f; }

extern "C" void kernel_launch(void* const* d_in, const int* in_sizes, int n_in,
                              void* d_out, int out_size) {
    // Unit detection (elements vs bytes) via the 100-element diag array.
    int smin = 0x7fffffff;
    for (int i = 0; i < n_in; ++i)
        if (in_sizes[i] < smin) smin = in_sizes[i];

    int unit = 0;
    if (smin == DIM)          unit = 1;
    else if (smin == DIM * 4) unit = 4;

    const float* xre = nullptr; const float* xim = nullptr;
    const float* theta = nullptr; const float* phi = nullptr;
    const float* diag = nullptr;
    int nbatch = 0, big = 0;
    bool ok = (unit != 0) && (n_in == 5);

    if (ok) {
        int norm[8];
        int diag_slot = -1;
        for (int i = 0; i < n_in; ++i) {
            norm[i] = in_sizes[i] / unit;
            if (norm[i] == DIM) diag_slot = i;
            if (norm[i] > big) big = norm[i];
        }
        if (diag_slot == 0 && norm[1] == KBS && norm[2] == KBS) {
            // alphabetical metadata order: diag, phi, theta, x_re, x_im
            diag  = (const float*)d_in[0];
            phi   = (const float*)d_in[1];
            theta = (const float*)d_in[2];
            xre   = (const float*)d_in[3];
            xim   = (const float*)d_in[4];
        } else {
            for (int i = 0; i < n_in; ++i) {
                const float* p = (const float*)d_in[i];
                if (norm[i] == KBS)      { if (!theta) theta = p; else phi = p; }
                else if (norm[i] == DIM) { diag = p; }
                else if (norm[i] == big) { if (!xre) xre = p; else xim = p; }
            }
        }
        nbatch = big / NN;
        ok = xre && xim && theta && phi && diag &&
             nbatch > 0 && nbatch <= MAXB && (big == nbatch * NN);
    }

    if (!ok) {
        diag_mark_kernel<<<1, 1>>>((float*)d_out);
        return;
    }

    // ---- Output contract resolution (H*: complex64 was cast to float32) ----
    // mode 0 (real-only float stores)   : out_size == B*N*N      -> cap = want floats
    // mode 1 (interleaved float2 stores): out_size == 2*B*N*N    -> cap = 2*want floats
    //                                     out_size == 8*B*N*N(B) -> cap = 2*want floats
    // else: conservative real-only with cap = min(want, out_size) floats.
    const int want = nbatch * NN;
    int mode, out_floats;
    if      (out_size == want)     { mode = 0; out_floats = want; }
    else if (out_size == 2 * want) { mode = 1; out_floats = 2 * want; }
    else if (out_size == 8 * want) { mode = 1; out_floats = 2 * want; }
    else { mode = 0; out_floats = (out_size < want) ? out_size : want; }

    const int l_elems = nbatch * NN;   // extent of g_L actually used

    build_U<<<DIM, 64>>>(theta, phi, diag, KBS, KBS, DIM);
    gemm1_UX<<<nbatch, 512>>>(xre, xim, big, l_elems);
    gemm2_LUh<<<nbatch, 512>>>((float*)d_out, out_floats, mode, l_elems);
}